// round 14
// baseline (speedup 1.0000x reference)
#include <cuda_runtime.h>
#include <cuda_bf16.h>
#include <cstdint>

#define B_  4
#define C_  256
#define IC_ 128
#define N_  4096

// ---------------------------------------------------------------------------
// Scratch (device globals — allocations are banned)
// ---------------------------------------------------------------------------
__device__ __nv_bfloat16 g_Xb[(size_t)B_ * N_ * C_];    // 8.4 MB [token][ch]
__device__ __nv_bfloat16 g_Wb[512 * C_];                // QKV weights bf16
__device__ float         g_bf[512];                     // QKV bias
__device__ uint8_t       g_Qf[(size_t)B_ * N_ * IC_];   // 2 MB fp8 [token][k]
__device__ uint8_t       g_Kf[(size_t)B_ * N_ * IC_];   // 2 MB fp8 [token][k]
__device__ __nv_bfloat16 g_Vb[(size_t)B_ * N_ * C_];    // 8 MB bf16 [token][c]

// ---------------------------------------------------------------------------
// Helpers (baseline PTX: ldmatrix / mma / cp.async / fp8 cvt — sm_103 safe)
// ---------------------------------------------------------------------------
__device__ __forceinline__ uint32_t smem_u32(const void* p) {
    uint32_t a;
    asm("{ .reg .u64 t; cvta.to.shared.u64 t, %1; cvt.u32.u64 %0, t; }" : "=r"(a) : "l"(p));
    return a;
}
__device__ __forceinline__ void sts32(uint32_t addr, uint32_t v) {
    asm volatile("st.shared.b32 [%0], %1;" :: "r"(addr), "r"(v));
}
__device__ __forceinline__ void ldm_x4(uint32_t& r0, uint32_t& r1, uint32_t& r2, uint32_t& r3,
                                       uint32_t addr) {
    asm volatile("ldmatrix.sync.aligned.m8n8.x4.shared.b16 {%0,%1,%2,%3}, [%4];"
                 : "=r"(r0), "=r"(r1), "=r"(r2), "=r"(r3) : "r"(addr));
}
__device__ __forceinline__ void ldm_x2(uint32_t& r0, uint32_t& r1, uint32_t addr) {
    asm volatile("ldmatrix.sync.aligned.m8n8.x2.shared.b16 {%0,%1}, [%2];"
                 : "=r"(r0), "=r"(r1) : "r"(addr));
}
__device__ __forceinline__ void ldm_x4_t(uint32_t& r0, uint32_t& r1, uint32_t& r2, uint32_t& r3,
                                         uint32_t addr) {
    asm volatile("ldmatrix.sync.aligned.m8n8.x4.trans.shared.b16 {%0,%1,%2,%3}, [%4];"
                 : "=r"(r0), "=r"(r1), "=r"(r2), "=r"(r3) : "r"(addr));
}
__device__ __forceinline__ void mma_bf16(float* d, uint32_t a0, uint32_t a1, uint32_t a2,
                                         uint32_t a3, uint32_t b0, uint32_t b1) {
    asm volatile("mma.sync.aligned.m16n8k16.row.col.f32.bf16.bf16.f32 "
                 "{%0,%1,%2,%3}, {%4,%5,%6,%7}, {%8,%9}, {%0,%1,%2,%3};"
                 : "+f"(d[0]), "+f"(d[1]), "+f"(d[2]), "+f"(d[3])
                 : "r"(a0), "r"(a1), "r"(a2), "r"(a3), "r"(b0), "r"(b1));
}
__device__ __forceinline__ void mma_fp8(float* d, uint32_t a0, uint32_t a1, uint32_t a2,
                                        uint32_t a3, uint32_t b0, uint32_t b1) {
    asm volatile("mma.sync.aligned.m16n8k32.row.col.f32.e4m3.e4m3.f32 "
                 "{%0,%1,%2,%3}, {%4,%5,%6,%7}, {%8,%9}, {%0,%1,%2,%3};"
                 : "+f"(d[0]), "+f"(d[1]), "+f"(d[2]), "+f"(d[3])
                 : "r"(a0), "r"(a1), "r"(a2), "r"(a3), "r"(b0), "r"(b1));
}
__device__ __forceinline__ void cp16(uint32_t s, const void* g) {
    asm volatile("cp.async.cg.shared.global [%0], [%1], 16;" :: "r"(s), "l"(g));
}
#define CP_COMMIT() asm volatile("cp.async.commit_group;" ::: "memory")
#define CP_WAIT1()  asm volatile("cp.async.wait_group 1;"  ::: "memory")
#define CP_WAIT0()  asm volatile("cp.async.wait_group 0;"  ::: "memory")

__device__ __forceinline__ uint32_t swz128(uint32_t o) { return o ^ (((o >> 7) & 7) << 4); }
__device__ __forceinline__ uint32_t swz256(uint32_t o) { return o ^ (((o >> 8) & 7) << 4); }
__device__ __forceinline__ uint32_t swz512(uint32_t o) { return o ^ (((o >> 9) & 7) << 4); }

// pitch-80 layout for 64-byte logical rows (P tile): conflict-free ldmatrix
#define PITCH64 80u

__device__ __forceinline__ uint32_t pk_bf2(float a, float b) {
    __nv_bfloat162 t = __float22bfloat162_rn(make_float2(a, b));
    return *reinterpret_cast<uint32_t*>(&t);
}
__device__ __forceinline__ uint16_t pk_f8(float lo, float hi) {
    uint16_t r;
    asm("cvt.rn.satfinite.e4m3x2.f32 %0, %1, %2;" : "=h"(r) : "f"(hi), "f"(lo));
    return r;
}

// ---------------------------------------------------------------------------
// Kernel 0a: transpose-convert x [B,C,N] fp32 -> g_Xb [B*N, C] bf16
// ---------------------------------------------------------------------------
__global__ __launch_bounds__(256) void xpose_kernel(const float* __restrict__ x)
{
    __shared__ float tile[32][132];
    const int c0 = blockIdx.x * 32, n0 = blockIdx.y * 128, b = blockIdx.z;
    const int t = threadIdx.x;

    const float* xb = x + ((size_t)b * C_ + c0) * N_ + n0;
#pragma unroll
    for (int r = 0; r < 4; r++) {
        int idx = t + r * 256;
        int cc = idx >> 5, nn = (idx & 31) * 4;
        float4 v = *reinterpret_cast<const float4*>(xb + (size_t)cc * N_ + nn);
        *reinterpret_cast<float4*>(&tile[cc][nn]) = v;
    }
    __syncthreads();
#pragma unroll
    for (int r = 0; r < 4; r++) {
        int idx = t + r * 256;
        int nn = idx >> 3, ck = (idx & 7) * 4;
        uint2 w;
        w.x = pk_bf2(tile[ck][nn],     tile[ck + 1][nn]);
        w.y = pk_bf2(tile[ck + 2][nn], tile[ck + 3][nn]);
        *reinterpret_cast<uint2*>(&g_Xb[(size_t)(b * N_ + n0 + nn) * C_ + c0 + ck]) = w;
    }
}

// ---------------------------------------------------------------------------
// Kernel 0b: convert QKV weights + bias to bf16/f32
// ---------------------------------------------------------------------------
__global__ __launch_bounds__(256) void wprep_kernel(
    const float* __restrict__ Wq, const float* __restrict__ bq,
    const float* __restrict__ Wk, const float* __restrict__ bk,
    const float* __restrict__ Wv, const float* __restrict__ bv)
{
    const int q = blockIdx.x * 256 + threadIdx.x;
#pragma unroll
    for (int r = 0; r < 2; r++) {
        int idx = q + r * 16384;
        int row = idx >> 6, c4 = (idx & 63) * 4;
        const float* src;
        if (row < 128)      src = Wq + (size_t)row * C_;
        else if (row < 256) src = Wk + (size_t)(row - 128) * C_;
        else                src = Wv + (size_t)(row - 256) * C_;
        float4 v = *reinterpret_cast<const float4*>(src + c4);
        uint2 w;
        w.x = pk_bf2(v.x, v.y);
        w.y = pk_bf2(v.z, v.w);
        *reinterpret_cast<uint2*>(&g_Wb[row * C_ + c4]) = w;
    }
    if (q < 512) {
        float bval;
        if (q < 128)      bval = bq[q];
        else if (q < 256) bval = bk[q - 128];
        else              bval = bv[q - 256];
        g_bf[q] = bval;
    }
}

// ---------------------------------------------------------------------------
// Kernel 1: QKV projection (bf16 HMMA).
// n-tile 0 -> Qf fp8, 1 -> Kf fp8, 2/3 -> Vb bf16 direct
// ---------------------------------------------------------------------------
#define PROJ_SMEM (65536 + 1024)
__global__ __launch_bounds__(256) void proj_kernel()
{
    extern __shared__ char dsm[];
    uintptr_t abp = (reinterpret_cast<uintptr_t>(dsm) + 1023) & ~uintptr_t(1023);
    const uint32_t As = smem_u32(reinterpret_cast<char*>(abp));
    const uint32_t Bs = As + 32768;

    const int t = threadIdx.x, wid = t >> 5, lane = t & 31;
    const int wm = wid & 3, wn = wid >> 2;
    const int rlo = lane & 15;
    const int rq = lane >> 2, qc = (lane & 3) * 2;
    const uint32_t colB0 = (uint32_t)((lane >> 4) << 4);
    const int n0 = blockIdx.x * 128;
    const int m0 = blockIdx.y * 128;

    float d[2][8][4];
#pragma unroll
    for (int mt = 0; mt < 2; mt++)
#pragma unroll
        for (int nt = 0; nt < 8; nt++)
#pragma unroll
            for (int e = 0; e < 4; e++) d[mt][nt][e] = 0.f;

    for (int chunk = 0; chunk < 2; chunk++) {
        const int ch0 = chunk * 128;
#pragma unroll
        for (int r = 0; r < 8; r++) {
            int idx = t + r * 256;
            int row = idx >> 4, ch = idx & 15;
            cp16(As + swz256((uint32_t)(row * 256 + ch * 16)),
                 g_Xb + (size_t)(m0 + row) * C_ + ch0 + ch * 8);
        }
#pragma unroll
        for (int r = 0; r < 8; r++) {
            int idx = t + r * 256;
            int row = idx >> 4, ch = idx & 15;
            cp16(Bs + swz256((uint32_t)(row * 256 + ch * 16)),
                 g_Wb + (size_t)(n0 + row) * C_ + ch0 + ch * 8);
        }
        CP_COMMIT();
        CP_WAIT0();
        __syncthreads();

#pragma unroll
        for (int kk = 0; kk < 8; kk++) {
            uint32_t a[2][4];
#pragma unroll
            for (int mt = 0; mt < 2; mt++) {
                uint32_t o = (uint32_t)((wm * 32 + mt * 16 + rlo) * 256 + kk * 32) + colB0;
                ldm_x4(a[mt][0], a[mt][1], a[mt][2], a[mt][3], As + swz256(o));
            }
            uint32_t bb[4][4];
#pragma unroll
            for (int np = 0; np < 4; np++) {
                uint32_t o = (uint32_t)((wn * 64 + np * 16 + rlo) * 256 + kk * 32) + colB0;
                ldm_x4(bb[np][0], bb[np][1], bb[np][2], bb[np][3], Bs + swz256(o));
            }
#pragma unroll
            for (int mt = 0; mt < 2; mt++)
#pragma unroll
                for (int nt = 0; nt < 8; nt++) {
                    int np = nt >> 1, hi = nt & 1;
                    mma_bf16(d[mt][nt], a[mt][0], a[mt][1], a[mt][2], a[mt][3],
                             bb[np][hi], bb[np][2 + hi]);
                }
        }
        __syncthreads();
    }

    if (blockIdx.x < 2) {
        uint8_t* dst = (blockIdx.x == 0) ? g_Qf : g_Kf;
#pragma unroll
        for (int nt = 0; nt < 8; nt++) {
            int jl = wn * 64 + nt * 8 + qc;
            float b0 = g_bf[n0 + jl], b1 = g_bf[n0 + jl + 1];
#pragma unroll
            for (int mt = 0; mt < 2; mt++) {
                int ib = m0 + wm * 32 + mt * 16 + rq;
                uint16_t w0 = pk_f8(d[mt][nt][0] + b0, d[mt][nt][1] + b1);
                uint16_t w1 = pk_f8(d[mt][nt][2] + b0, d[mt][nt][3] + b1);
                *reinterpret_cast<uint16_t*>(&dst[(size_t)ib * IC_ + jl])       = w0;
                *reinterpret_cast<uint16_t*>(&dst[(size_t)(ib + 8) * IC_ + jl]) = w1;
            }
        }
    } else {
        const int cb = (blockIdx.x == 2) ? 0 : 128;
#pragma unroll
        for (int nt = 0; nt < 8; nt++) {
            int jl = wn * 64 + nt * 8 + qc;
            float b0 = g_bf[n0 + jl], b1 = g_bf[n0 + jl + 1];
#pragma unroll
            for (int mt = 0; mt < 2; mt++) {
                int ib = m0 + wm * 32 + mt * 16 + rq;
                uint32_t w0 = pk_bf2(d[mt][nt][0] + b0, d[mt][nt][1] + b1);
                uint32_t w1 = pk_bf2(d[mt][nt][2] + b0, d[mt][nt][3] + b1);
                *reinterpret_cast<uint32_t*>(&g_Vb[(size_t)ib * C_ + cb + jl])       = w0;
                *reinterpret_cast<uint32_t*>(&g_Vb[(size_t)(ib + 8) * C_ + cb + jl]) = w1;
            }
        }
    }
}

// ---------------------------------------------------------------------------
// Kernel 2: fused flash attention — 32-row CTAs, j-chunk 32, 4 CTAs/SM target.
// fp8 MMA1 (QK), bf16 MMA2 (PV). Round-11 proven 2-barrier schedule.
// Q [32][128B] swz128; K 2x[32][128B] swz128; P [32 rows pitch80] bf16;
// V 2x[32][512B] swz512.
// ---------------------------------------------------------------------------
#define QS_OFF  0u              // 4096
#define PS_OFF  4096u           // 32*80 = 2560
#define KS_OFF  6656u           // 2 x 4096
#define VS_OFF  14848u          // 2 x 16384 -> end 47616
#define LS_OFF  47616u          // 32 f32
#define FLASH_SMEM (47744 + 1024)

__global__ void __launch_bounds__(256, 4) flash_kernel(
    const float* __restrict__ x, const float* __restrict__ gamma,
    float* __restrict__ out)
{
    extern __shared__ char dsm[];
    uintptr_t abp = (reinterpret_cast<uintptr_t>(dsm) + 1023) & ~uintptr_t(1023);
    const uint32_t S = smem_u32(reinterpret_cast<char*>(abp));
    float* fbase = reinterpret_cast<float*>(abp);
    float* lS    = fbase + LS_OFF / 4;

    const int t = threadIdx.x, wid = t >> 5, lane = t & 31;
    const int wm = wid & 1, wj = wid >> 1;          // MMA1: 2 row-groups x 4 j-groups
    const int rlo = lane & 15;
    const int rq = lane >> 2, qc = (lane & 3) * 2;
    const uint32_t colB0 = (uint32_t)((lane >> 4) << 4);
    const int b = blockIdx.y, i0 = blockIdx.x * 32;

    const uint8_t* Qg = g_Qf + (size_t)(b * N_ + i0) * IC_;
    const uint8_t* Kg = g_Kf + (size_t)b * N_ * IC_;
    const __nv_bfloat16* Vg = g_Vb + (size_t)b * N_ * C_;

    // out accumulators: 32 rows x 32 c per warp (32 regs)
    float o2[2][4][4];
#pragma unroll
    for (int a = 0; a < 2; a++)
#pragma unroll
        for (int nn = 0; nn < 4; nn++)
#pragma unroll
            for (int e = 0; e < 4; e++) o2[a][nn][e] = 0.f;

    float lp[2] = {0.f, 0.f};

    auto load_k = [&](int jc) {
        const uint32_t ks = KS_OFF + (uint32_t)(jc & 1) * 4096u;
        int row = t >> 3, ch = t & 7;
        cp16(S + ks + swz128((uint32_t)(row * 128 + ch * 16)),
             Kg + (size_t)(jc * 32 + row) * IC_ + ch * 16);
    };
    auto load_v = [&](int jc) {
        const uint32_t vs = VS_OFF + (uint32_t)(jc & 1) * 16384u;
#pragma unroll
        for (int r = 0; r < 4; r++) {
            int idx = t + r * 256;
            int row = idx >> 5, ch = idx & 31;
            cp16(S + vs + swz512((uint32_t)(row * 512 + ch * 16)),
                 Vg + (size_t)(jc * 32 + row) * C_ + ch * 8);
        }
    };

    // prologue: [Q + K(0)] group, then [V(0)] group
    {
        int row = t >> 3, ch = t & 7;
        cp16(S + QS_OFF + swz128((uint32_t)(row * 128 + ch * 16)),
             Qg + (size_t)row * IC_ + ch * 16);
    }
    load_k(0);
    CP_COMMIT();
    load_v(0);
    CP_COMMIT();

    const float SCL = 0.12753785f;   // 128^-0.5 * log2(e)

    for (int c = 0; c < 128; c++) {
        const uint32_t ks = KS_OFF + (uint32_t)(c & 1) * 4096u;
        const uint32_t vs = VS_OFF + (uint32_t)(c & 1) * 16384u;

        CP_WAIT1();        // K(c) ready; V(c) may be in flight
        __syncthreads();   // K visible; P(c-1) consumed

        // ---- MMA1: S' = Q K^T (16 rows x 8 j per warp, fp8 k32 x4) ----
        float d1[4];
#pragma unroll
        for (int e = 0; e < 4; e++) d1[e] = 0.f;

#pragma unroll
        for (int kk = 0; kk < 4; kk++) {
            uint32_t a0[4];
            {
                uint32_t o = (uint32_t)((wm * 16 + rlo) * 128 + kk * 32) + colB0;
                ldm_x4(a0[0], a0[1], a0[2], a0[3], S + QS_OFF + swz128(o));
            }
            uint32_t bb[2];
            {
                uint32_t o = (uint32_t)((wj * 8 + (lane & 7)) * 128 + kk * 32) +
                             (uint32_t)(((lane >> 3) & 1) * 16);
                ldm_x2(bb[0], bb[1], S + ks + swz128(o));
            }
            mma_fp8(d1, a0[0], a0[1], a0[2], a0[3], bb[0], bb[1]);
        }

        // ---- P = exp2(SCL*S') -> bf16 into Ps (pitch-80); l partials ----
#pragma unroll
        for (int hi = 0; hi < 2; hi++) {
            int row = wm * 16 + hi * 8 + rq;
            float e0 = exp2f(d1[hi * 2]     * SCL);
            float e1 = exp2f(d1[hi * 2 + 1] * SCL);
            lp[hi] += e0 + e1;
            sts32(S + PS_OFF + (uint32_t)row * PITCH64 + (uint32_t)((wj * 8 + qc) * 2),
                  pk_bf2(e0, e1));
        }

        CP_WAIT0();        // V(c) ready
        __syncthreads();   // V + P visible

        if (c + 1 < 128) {
            load_k(c + 1); CP_COMMIT();
            load_v(c + 1); CP_COMMIT();
        }

        // ---- MMA2: out += P (bf16 32x32) * V (bf16 32x256), slice wid*32 ----
#pragma unroll
        for (int kk = 0; kk < 2; kk++) {
            uint32_t av[2][4];
#pragma unroll
            for (int mt2 = 0; mt2 < 2; mt2++) {
                uint32_t o = (uint32_t)(mt2 * 16 + rlo) * PITCH64 +
                             (uint32_t)(kk * 32) + colB0;
                ldm_x4(av[mt2][0], av[mt2][1], av[mt2][2], av[mt2][3], S + PS_OFF + o);
            }
            uint32_t bv[2][4];
#pragma unroll
            for (int np = 0; np < 2; np++) {
                uint32_t o = (uint32_t)((kk * 16 + rlo) * 512 + wid * 64 + np * 32) + colB0;
                ldm_x4_t(bv[np][0], bv[np][1], bv[np][2], bv[np][3], S + vs + swz512(o));
            }
#pragma unroll
            for (int mt2 = 0; mt2 < 2; mt2++)
#pragma unroll
                for (int nn = 0; nn < 4; nn++) {
                    int np = nn >> 1, hi = (nn & 1) * 2;
                    mma_bf16(o2[mt2][nn], av[mt2][0], av[mt2][1], av[mt2][2], av[mt2][3],
                             bv[np][hi], bv[np][hi + 1]);
                }
        }
    }

    // ---- combine l partials once (4 wj warps per row) ----
    __syncthreads();
#pragma unroll
    for (int hi = 0; hi < 2; hi++) {
        float v = lp[hi];
        v += __shfl_xor_sync(0xffffffffu, v, 1);
        v += __shfl_xor_sync(0xffffffffu, v, 2);
        if ((lane & 3) == 0)
            fbase[wj * 32 + wm * 16 + hi * 8 + rq] = v;
    }
    __syncthreads();
    if (t < 32)
        lS[t] = 1.f / (fbase[t] + fbase[32 + t] + fbase[64 + t] + fbase[96 + t]);
    __syncthreads();

    // ---- epilogue: normalize, transpose via smem (pitch 36), gamma*o + 2x ----
    float* sEpi = fbase;
    const int W = 36;
#pragma unroll
    for (int mt2 = 0; mt2 < 2; mt2++) {
        int r0 = mt2 * 16 + rq;
        float inv0 = lS[r0];
        float inv1 = lS[r0 + 8];
#pragma unroll
        for (int nn = 0; nn < 4; nn++) {
            int cc = wid * 32 + nn * 8 + qc;
            sEpi[cc * W + r0]           = o2[mt2][nn][0] * inv0;
            sEpi[(cc + 1) * W + r0]     = o2[mt2][nn][1] * inv0;
            sEpi[cc * W + r0 + 8]       = o2[mt2][nn][2] * inv1;
            sEpi[(cc + 1) * W + r0 + 8] = o2[mt2][nn][3] * inv1;
        }
    }
    __syncthreads();

    const float gm = gamma[0];
#pragma unroll
    for (int r = 0; r < 8; r++) {
        int idx = t + r * 256;
        int cc = idx >> 3, mq = (idx & 7) * 4;
        float4 sv = *reinterpret_cast<const float4*>(&sEpi[cc * W + mq]);
        size_t gi = ((size_t)(b * C_ + cc)) * N_ + i0 + mq;
        float4 xv = *reinterpret_cast<const float4*>(x + gi);
        float4 o;
        o.x = gm * sv.x + 2.f * xv.x;
        o.y = gm * sv.y + 2.f * xv.y;
        o.z = gm * sv.z + 2.f * xv.z;
        o.w = gm * sv.w + 2.f * xv.w;
        *reinterpret_cast<float4*>(out + gi) = o;
    }
}

// ---------------------------------------------------------------------------
extern "C" void kernel_launch(void* const* d_in, const int* in_sizes, int n_in,
                              void* d_out, int out_size)
{
    const float* x     = (const float*)d_in[0];
    const float* Wq    = (const float*)d_in[1];
    const float* bq    = (const float*)d_in[2];
    const float* Wk    = (const float*)d_in[3];
    const float* bk    = (const float*)d_in[4];
    const float* Wv    = (const float*)d_in[5];
    const float* bv    = (const float*)d_in[6];
    const float* gamma = (const float*)d_in[7];
    float* out = (float*)d_out;

    cudaFuncSetAttribute(proj_kernel,  cudaFuncAttributeMaxDynamicSharedMemorySize, PROJ_SMEM);
    cudaFuncSetAttribute(flash_kernel, cudaFuncAttributeMaxDynamicSharedMemorySize, FLASH_SMEM);

    xpose_kernel<<<dim3(C_ / 32, N_ / 128, B_), 256>>>(x);
    wprep_kernel<<<64, 256>>>(Wq, bq, Wk, bk, Wv, bv);
    proj_kernel<<<dim3(4, (B_ * N_) / 128), 256, PROJ_SMEM>>>();
    flash_kernel<<<dim3(N_ / 32, B_), 256, FLASH_SMEM>>>(x, gamma, out);
}

// round 15
// speedup vs baseline: 1.1677x; 1.1677x over previous
#include <cuda_runtime.h>
#include <cuda_bf16.h>
#include <cstdint>

#define B_  4
#define C_  256
#define IC_ 128
#define N_  4096

// ---------------------------------------------------------------------------
// Scratch (device globals — allocations are banned)
// ---------------------------------------------------------------------------
__device__ __nv_bfloat16 g_Xb[(size_t)B_ * N_ * C_];    // 8.4 MB [token][ch]
__device__ __nv_bfloat16 g_Wb[512 * C_];                // QKV weights bf16
__device__ float         g_bf[512];                     // QKV bias
__device__ uint8_t       g_Qf[(size_t)B_ * N_ * IC_];   // 2 MB fp8 [token][k]
__device__ uint8_t       g_Kf[(size_t)B_ * N_ * IC_];   // 2 MB fp8 [token][k]
__device__ __nv_bfloat16 g_Vb[(size_t)B_ * N_ * C_];    // 8 MB bf16 [token][c]

// ---------------------------------------------------------------------------
// Helpers (baseline PTX: ldmatrix / mma / cp.async / fp8 cvt — sm_103 safe)
// ---------------------------------------------------------------------------
__device__ __forceinline__ uint32_t smem_u32(const void* p) {
    uint32_t a;
    asm("{ .reg .u64 t; cvta.to.shared.u64 t, %1; cvt.u32.u64 %0, t; }" : "=r"(a) : "l"(p));
    return a;
}
__device__ __forceinline__ void sts32(uint32_t addr, uint32_t v) {
    asm volatile("st.shared.b32 [%0], %1;" :: "r"(addr), "r"(v));
}
__device__ __forceinline__ void ldm_x4(uint32_t& r0, uint32_t& r1, uint32_t& r2, uint32_t& r3,
                                       uint32_t addr) {
    asm volatile("ldmatrix.sync.aligned.m8n8.x4.shared.b16 {%0,%1,%2,%3}, [%4];"
                 : "=r"(r0), "=r"(r1), "=r"(r2), "=r"(r3) : "r"(addr));
}
__device__ __forceinline__ void ldm_x4_t(uint32_t& r0, uint32_t& r1, uint32_t& r2, uint32_t& r3,
                                         uint32_t addr) {
    asm volatile("ldmatrix.sync.aligned.m8n8.x4.trans.shared.b16 {%0,%1,%2,%3}, [%4];"
                 : "=r"(r0), "=r"(r1), "=r"(r2), "=r"(r3) : "r"(addr));
}
__device__ __forceinline__ void mma_bf16(float* d, uint32_t a0, uint32_t a1, uint32_t a2,
                                         uint32_t a3, uint32_t b0, uint32_t b1) {
    asm volatile("mma.sync.aligned.m16n8k16.row.col.f32.bf16.bf16.f32 "
                 "{%0,%1,%2,%3}, {%4,%5,%6,%7}, {%8,%9}, {%0,%1,%2,%3};"
                 : "+f"(d[0]), "+f"(d[1]), "+f"(d[2]), "+f"(d[3])
                 : "r"(a0), "r"(a1), "r"(a2), "r"(a3), "r"(b0), "r"(b1));
}
__device__ __forceinline__ void mma_fp8(float* d, uint32_t a0, uint32_t a1, uint32_t a2,
                                        uint32_t a3, uint32_t b0, uint32_t b1) {
    asm volatile("mma.sync.aligned.m16n8k32.row.col.f32.e4m3.e4m3.f32 "
                 "{%0,%1,%2,%3}, {%4,%5,%6,%7}, {%8,%9}, {%0,%1,%2,%3};"
                 : "+f"(d[0]), "+f"(d[1]), "+f"(d[2]), "+f"(d[3])
                 : "r"(a0), "r"(a1), "r"(a2), "r"(a3), "r"(b0), "r"(b1));
}
__device__ __forceinline__ void cp16(uint32_t s, const void* g) {
    asm volatile("cp.async.cg.shared.global [%0], [%1], 16;" :: "r"(s), "l"(g));
}
#define CP_COMMIT() asm volatile("cp.async.commit_group;" ::: "memory")
#define CP_WAIT1()  asm volatile("cp.async.wait_group 1;"  ::: "memory")
#define CP_WAIT0()  asm volatile("cp.async.wait_group 0;"  ::: "memory")

__device__ __forceinline__ uint32_t swz128(uint32_t o) { return o ^ (((o >> 7) & 7) << 4); }
__device__ __forceinline__ uint32_t swz512(uint32_t o) { return o ^ (((o >> 9) & 7) << 4); }

__device__ __forceinline__ uint32_t pk_bf2(float a, float b) {
    __nv_bfloat162 t = __float22bfloat162_rn(make_float2(a, b));
    return *reinterpret_cast<uint32_t*>(&t);
}
__device__ __forceinline__ uint16_t pk_f8(float lo, float hi) {
    uint16_t r;
    asm("cvt.rn.satfinite.e4m3x2.f32 %0, %1, %2;" : "=h"(r) : "f"(hi), "f"(lo));
    return r;
}

// ---------------------------------------------------------------------------
// Kernel 0: prep — transpose-convert x -> g_Xb, AND (first 64 CTAs) convert
// W/bias -> g_Wb / g_bf.  (merged xpose + wprep: one launch)
// ---------------------------------------------------------------------------
__global__ __launch_bounds__(256) void prep_kernel(
    const float* __restrict__ x,
    const float* __restrict__ Wq, const float* __restrict__ bq,
    const float* __restrict__ Wk, const float* __restrict__ bk,
    const float* __restrict__ Wv, const float* __restrict__ bv)
{
    __shared__ float tile[32][132];
    const int c0 = blockIdx.x * 32, n0 = blockIdx.y * 128, b = blockIdx.z;
    const int t = threadIdx.x;

    // ---- wprep portion on the first 64 CTAs ----
    const int flat = (blockIdx.z * 32 + blockIdx.y) * 8 + blockIdx.x;
    if (flat < 64) {
        const int q = flat * 256 + t;
#pragma unroll
        for (int r = 0; r < 2; r++) {
            int idx = q + r * 16384;
            int row = idx >> 6, c4 = (idx & 63) * 4;
            const float* src;
            if (row < 128)      src = Wq + (size_t)row * C_;
            else if (row < 256) src = Wk + (size_t)(row - 128) * C_;
            else                src = Wv + (size_t)(row - 256) * C_;
            float4 v = *reinterpret_cast<const float4*>(src + c4);
            uint2 w;
            w.x = pk_bf2(v.x, v.y);
            w.y = pk_bf2(v.z, v.w);
            *reinterpret_cast<uint2*>(&g_Wb[row * C_ + c4]) = w;
        }
        if (q < 512) {
            float bval;
            if (q < 128)      bval = bq[q];
            else if (q < 256) bval = bk[q - 128];
            else              bval = bv[q - 256];
            g_bf[q] = bval;
        }
    }

    // ---- xpose portion (all CTAs) ----
    const float* xb = x + ((size_t)b * C_ + c0) * N_ + n0;
#pragma unroll
    for (int r = 0; r < 4; r++) {
        int idx = t + r * 256;
        int cc = idx >> 5, nn = (idx & 31) * 4;
        float4 v = *reinterpret_cast<const float4*>(xb + (size_t)cc * N_ + nn);
        *reinterpret_cast<float4*>(&tile[cc][nn]) = v;
    }
    __syncthreads();
#pragma unroll
    for (int r = 0; r < 4; r++) {
        int idx = t + r * 256;
        int nn = idx >> 3, ck = (idx & 7) * 4;
        uint2 w;
        w.x = pk_bf2(tile[ck][nn],     tile[ck + 1][nn]);
        w.y = pk_bf2(tile[ck + 2][nn], tile[ck + 3][nn]);
        *reinterpret_cast<uint2*>(&g_Xb[(size_t)(b * N_ + n0 + nn) * C_ + c0 + ck]) = w;
    }
}

// ---------------------------------------------------------------------------
// Kernel 1: QKV projection (bf16 HMMA), PIPELINED: 4 K=64 sub-stages,
// double-buffered; load(s+1) overlaps compute(s).
// n-tile 0 -> Qf fp8, 1 -> Kf fp8, 2/3 -> Vb bf16 direct
// ---------------------------------------------------------------------------
#define PROJ_SMEM (65536 + 1024)
__global__ __launch_bounds__(256) void proj_kernel()
{
    extern __shared__ char dsm[];
    uintptr_t abp = (reinterpret_cast<uintptr_t>(dsm) + 1023) & ~uintptr_t(1023);
    const uint32_t SB = smem_u32(reinterpret_cast<char*>(abp));
    // buffers: [A0 16K][B0 16K][A1 16K][B1 16K]

    const int t = threadIdx.x, wid = t >> 5, lane = t & 31;
    const int wm = wid & 3, wn = wid >> 2;
    const int rlo = lane & 15;
    const int rq = lane >> 2, qc = (lane & 3) * 2;
    const uint32_t colB0 = (uint32_t)((lane >> 4) << 4);
    const int n0 = blockIdx.x * 128;
    const int m0 = blockIdx.y * 128;

    float d[2][8][4];
#pragma unroll
    for (int mt = 0; mt < 2; mt++)
#pragma unroll
        for (int nt = 0; nt < 8; nt++)
#pragma unroll
            for (int e = 0; e < 4; e++) d[mt][nt][e] = 0.f;

    auto load_stage = [&](int s) {
        const uint32_t as = SB + (uint32_t)(s & 1) * 32768u;
        const uint32_t bs = as + 16384u;
        const int ch0 = s * 64;
#pragma unroll
        for (int r = 0; r < 4; r++) {
            int idx = t + r * 256;
            int row = idx >> 3, ch = idx & 7;           // 128 rows x 8 chunks
            cp16(as + swz128((uint32_t)(row * 128 + ch * 16)),
                 g_Xb + (size_t)(m0 + row) * C_ + ch0 + ch * 8);
        }
#pragma unroll
        for (int r = 0; r < 4; r++) {
            int idx = t + r * 256;
            int row = idx >> 3, ch = idx & 7;
            cp16(bs + swz128((uint32_t)(row * 128 + ch * 16)),
                 g_Wb + (size_t)(n0 + row) * C_ + ch0 + ch * 8);
        }
        CP_COMMIT();
    };

    load_stage(0);

    for (int s = 0; s < 4; s++) {
        const uint32_t as = SB + (uint32_t)(s & 1) * 32768u;
        const uint32_t bs = as + 16384u;

        CP_WAIT0();
        __syncthreads();          // stage s visible; buffer (s+1)&1 reads done

        if (s + 1 < 4) load_stage(s + 1);

#pragma unroll
        for (int kk = 0; kk < 4; kk++) {
            uint32_t a[2][4];
#pragma unroll
            for (int mt = 0; mt < 2; mt++) {
                uint32_t o = (uint32_t)((wm * 32 + mt * 16 + rlo) * 128 + kk * 32) + colB0;
                ldm_x4(a[mt][0], a[mt][1], a[mt][2], a[mt][3], as + swz128(o));
            }
            uint32_t bb[4][4];
#pragma unroll
            for (int np = 0; np < 4; np++) {
                uint32_t o = (uint32_t)((wn * 64 + np * 16 + rlo) * 128 + kk * 32) + colB0;
                ldm_x4(bb[np][0], bb[np][1], bb[np][2], bb[np][3], bs + swz128(o));
            }
#pragma unroll
            for (int mt = 0; mt < 2; mt++)
#pragma unroll
                for (int nt = 0; nt < 8; nt++) {
                    int np = nt >> 1, hi = nt & 1;
                    mma_bf16(d[mt][nt], a[mt][0], a[mt][1], a[mt][2], a[mt][3],
                             bb[np][hi], bb[np][2 + hi]);
                }
        }
    }

    if (blockIdx.x < 2) {
        // Q / K: fp8 [token][128], direct u16 stores
        uint8_t* dst = (blockIdx.x == 0) ? g_Qf : g_Kf;
#pragma unroll
        for (int nt = 0; nt < 8; nt++) {
            int jl = wn * 64 + nt * 8 + qc;
            float b0 = g_bf[n0 + jl], b1 = g_bf[n0 + jl + 1];
#pragma unroll
            for (int mt = 0; mt < 2; mt++) {
                int ib = m0 + wm * 32 + mt * 16 + rq;
                uint16_t w0 = pk_f8(d[mt][nt][0] + b0, d[mt][nt][1] + b1);
                uint16_t w1 = pk_f8(d[mt][nt][2] + b0, d[mt][nt][3] + b1);
                *reinterpret_cast<uint16_t*>(&dst[(size_t)ib * IC_ + jl])       = w0;
                *reinterpret_cast<uint16_t*>(&dst[(size_t)(ib + 8) * IC_ + jl]) = w1;
            }
        }
    } else {
        // V: bf16 [token][256] direct stores
        const int cb = (blockIdx.x == 2) ? 0 : 128;
#pragma unroll
        for (int nt = 0; nt < 8; nt++) {
            int jl = wn * 64 + nt * 8 + qc;
            float b0 = g_bf[n0 + jl], b1 = g_bf[n0 + jl + 1];
#pragma unroll
            for (int mt = 0; mt < 2; mt++) {
                int ib = m0 + wm * 32 + mt * 16 + rq;
                uint32_t w0 = pk_bf2(d[mt][nt][0] + b0, d[mt][nt][1] + b1);
                uint32_t w1 = pk_bf2(d[mt][nt][2] + b0, d[mt][nt][3] + b1);
                *reinterpret_cast<uint32_t*>(&g_Vb[(size_t)ib * C_ + cb + jl])       = w0;
                *reinterpret_cast<uint32_t*>(&g_Vb[(size_t)(ib + 8) * C_ + cb + jl]) = w1;
            }
        }
    }
}

// ---------------------------------------------------------------------------
// Kernel 2: fused flash attention — fp8 MMA1 (QK), bf16 MMA2 (PV).
// VERBATIM round-11 (best measured: 192.2 us).
// ---------------------------------------------------------------------------
#define QS_OFF  0u              // 8 KB
#define PS_OFF  8192u           // 8 KB
#define KS_OFF  16384u          // 2 x 8 KB
#define VS_OFF  32768u          // 2 x 32 KB -> end 98304
#define LS_OFF  98304u
#define FLASH_SMEM (98560 + 1024)

__global__ void __launch_bounds__(256, 2) flash_kernel(
    const float* __restrict__ x, const float* __restrict__ gamma,
    float* __restrict__ out)
{
    extern __shared__ char dsm[];
    uintptr_t abp = (reinterpret_cast<uintptr_t>(dsm) + 1023) & ~uintptr_t(1023);
    const uint32_t S = smem_u32(reinterpret_cast<char*>(abp));
    float* fbase = reinterpret_cast<float*>(abp);
    float* lS    = fbase + LS_OFF / 4;

    const int t = threadIdx.x, wid = t >> 5, lane = t & 31;
    const int wm = wid & 1, wj = wid >> 1;
    const int rlo = lane & 15;
    const int rq = lane >> 2, qc = (lane & 3) * 2;
    const uint32_t colB0 = (uint32_t)((lane >> 4) << 4);
    const int b = blockIdx.y, i0 = blockIdx.x * 64;

    const uint8_t* Qg = g_Qf + (size_t)(b * N_ + i0) * IC_;
    const uint8_t* Kg = g_Kf + (size_t)b * N_ * IC_;
    const __nv_bfloat16* Vg = g_Vb + (size_t)b * N_ * C_;

    float o2[4][4][4];
#pragma unroll
    for (int a = 0; a < 4; a++)
#pragma unroll
        for (int nn = 0; nn < 4; nn++)
#pragma unroll
            for (int e = 0; e < 4; e++) o2[a][nn][e] = 0.f;

    float lp[2][2] = {{0.f, 0.f}, {0.f, 0.f}};

    auto load_k = [&](int jc) {
        const uint32_t ks = KS_OFF + (uint32_t)(jc & 1) * 8192u;
#pragma unroll
        for (int r = 0; r < 2; r++) {
            int idx = t + r * 256;
            int row = idx >> 3, ch = idx & 7;
            cp16(S + ks + swz128((uint32_t)(row * 128 + ch * 16)),
                 Kg + (size_t)(jc * 64 + row) * IC_ + ch * 16);
        }
    };
    auto load_v = [&](int jc) {
        const uint32_t vs = VS_OFF + (uint32_t)(jc & 1) * 32768u;
#pragma unroll
        for (int r = 0; r < 8; r++) {
            int idx = t + r * 256;
            int row = idx >> 5, ch = idx & 31;
            cp16(S + vs + swz512((uint32_t)(row * 512 + ch * 16)),
                 Vg + (size_t)(jc * 64 + row) * C_ + ch * 8);
        }
    };

    // prologue: [Q + K(0)] group, then [V(0)] group
#pragma unroll
    for (int r = 0; r < 2; r++) {
        int idx = t + r * 256;
        int row = idx >> 3, ch = idx & 7;
        cp16(S + QS_OFF + swz128((uint32_t)(row * 128 + ch * 16)),
             Qg + (size_t)row * IC_ + ch * 16);
    }
    load_k(0);
    CP_COMMIT();
    load_v(0);
    CP_COMMIT();

    const float SCL = 0.12753785f;   // 128^-0.5 * log2(e)

    for (int c = 0; c < 64; c++) {
        const uint32_t ks = KS_OFF + (uint32_t)(c & 1) * 8192u;
        const uint32_t vs = VS_OFF + (uint32_t)(c & 1) * 32768u;

        CP_WAIT1();        // K(c) (older group) ready; V(c) may be in flight
        __syncthreads();   // K visible; P(c-1) consumed

        // ---- MMA1: S' = Q K^T  (64x64, fp8 m16n8k32 x4) ----
        float d1[2][2][4];
#pragma unroll
        for (int mt = 0; mt < 2; mt++)
#pragma unroll
            for (int nt = 0; nt < 2; nt++)
#pragma unroll
                for (int e = 0; e < 4; e++) d1[mt][nt][e] = 0.f;

#pragma unroll
        for (int kk = 0; kk < 4; kk++) {
            uint32_t a0[2][4];
#pragma unroll
            for (int mt = 0; mt < 2; mt++) {
                uint32_t o = (uint32_t)((wm * 32 + mt * 16 + rlo) * 128 + kk * 32) + colB0;
                ldm_x4(a0[mt][0], a0[mt][1], a0[mt][2], a0[mt][3], S + QS_OFF + swz128(o));
            }
            uint32_t bb[4];
            {
                uint32_t o = (uint32_t)((wj * 16 + rlo) * 128 + kk * 32) + colB0;
                ldm_x4(bb[0], bb[1], bb[2], bb[3], S + ks + swz128(o));
            }
#pragma unroll
            for (int mt = 0; mt < 2; mt++)
#pragma unroll
                for (int nt = 0; nt < 2; nt++)
                    mma_fp8(d1[mt][nt], a0[mt][0], a0[mt][1], a0[mt][2], a0[mt][3],
                            bb[nt], bb[2 + nt]);
        }

        // ---- P = exp2(SCL*S') -> bf16 into Ps (swz128); l partials ----
#pragma unroll
        for (int mt = 0; mt < 2; mt++)
#pragma unroll
            for (int hi = 0; hi < 2; hi++) {
                int row = wm * 32 + mt * 16 + hi * 8 + rq;
                float s = 0.f;
#pragma unroll
                for (int nt = 0; nt < 2; nt++) {
                    float e0 = exp2f(d1[mt][nt][hi * 2]     * SCL);
                    float e1 = exp2f(d1[mt][nt][hi * 2 + 1] * SCL);
                    s += e0 + e1;
                    sts32(S + PS_OFF + swz128((uint32_t)(row * 128 + (wj * 16 + nt * 8) * 2 + qc * 2)),
                          pk_bf2(e0, e1));
                }
                lp[mt][hi] += s;
            }

        CP_WAIT0();        // V(c) ready
        __syncthreads();   // V + P visible

        if (c + 1 < 64) {
            load_k(c + 1); CP_COMMIT();
            load_v(c + 1); CP_COMMIT();
        }

        // ---- MMA2: out += P (bf16 64x64) * V (bf16 64x256), slice wid*32 ----
#pragma unroll
        for (int kk = 0; kk < 4; kk++) {
            uint32_t av[4][4];
#pragma unroll
            for (int mt2 = 0; mt2 < 4; mt2++) {
                uint32_t o = (uint32_t)((mt2 * 16 + rlo) * 128 + kk * 32) + colB0;
                ldm_x4(av[mt2][0], av[mt2][1], av[mt2][2], av[mt2][3], S + PS_OFF + swz128(o));
            }
            uint32_t bv[2][4];
#pragma unroll
            for (int np = 0; np < 2; np++) {
                uint32_t o = (uint32_t)((kk * 16 + rlo) * 512 + wid * 64 + np * 32) + colB0;
                ldm_x4_t(bv[np][0], bv[np][1], bv[np][2], bv[np][3], S + vs + swz512(o));
            }
#pragma unroll
            for (int mt2 = 0; mt2 < 4; mt2++)
#pragma unroll
                for (int nn = 0; nn < 4; nn++) {
                    int np = nn >> 1, hi = (nn & 1) * 2;
                    mma_bf16(o2[mt2][nn], av[mt2][0], av[mt2][1], av[mt2][2], av[mt2][3],
                             bv[np][hi], bv[np][hi + 1]);
                }
        }
    }

    // ---- combine l partials once ----
    __syncthreads();
#pragma unroll
    for (int mt = 0; mt < 2; mt++)
#pragma unroll
        for (int hi = 0; hi < 2; hi++) {
            float v = lp[mt][hi];
            v += __shfl_xor_sync(0xffffffffu, v, 1);
            v += __shfl_xor_sync(0xffffffffu, v, 2);
            if ((lane & 3) == 0)
                fbase[wj * 64 + wm * 32 + mt * 16 + hi * 8 + rq] = v;
        }
    __syncthreads();
    if (t < 64)
        lS[t] = 1.f / (fbase[t] + fbase[64 + t] + fbase[128 + t] + fbase[192 + t]);
    __syncthreads();

    // ---- epilogue: normalize, transpose via smem, gamma*o + 2x ----
    float* sEpi = fbase;
    const int W = 68;
#pragma unroll
    for (int mt2 = 0; mt2 < 4; mt2++) {
        int r0 = mt2 * 16 + rq;
        float inv0 = lS[r0];
        float inv1 = lS[r0 + 8];
#pragma unroll
        for (int nn = 0; nn < 4; nn++) {
            int cc = wid * 32 + nn * 8 + qc;
            sEpi[cc * W + r0]           = o2[mt2][nn][0] * inv0;
            sEpi[(cc + 1) * W + r0]     = o2[mt2][nn][1] * inv0;
            sEpi[cc * W + r0 + 8]       = o2[mt2][nn][2] * inv1;
            sEpi[(cc + 1) * W + r0 + 8] = o2[mt2][nn][3] * inv1;
        }
    }
    __syncthreads();

    const float gm = gamma[0];
#pragma unroll
    for (int r = 0; r < 16; r++) {
        int idx = t + r * 256;
        int cc = idx >> 4, mq = (idx & 15) * 4;
        float4 sv = *reinterpret_cast<const float4*>(&sEpi[cc * W + mq]);
        size_t gi = ((size_t)(b * C_ + cc)) * N_ + i0 + mq;
        float4 xv = *reinterpret_cast<const float4*>(x + gi);
        float4 o;
        o.x = gm * sv.x + 2.f * xv.x;
        o.y = gm * sv.y + 2.f * xv.y;
        o.z = gm * sv.z + 2.f * xv.z;
        o.w = gm * sv.w + 2.f * xv.w;
        *reinterpret_cast<float4*>(out + gi) = o;
    }
}

// ---------------------------------------------------------------------------
extern "C" void kernel_launch(void* const* d_in, const int* in_sizes, int n_in,
                              void* d_out, int out_size)
{
    const float* x     = (const float*)d_in[0];
    const float* Wq    = (const float*)d_in[1];
    const float* bq    = (const float*)d_in[2];
    const float* Wk    = (const float*)d_in[3];
    const float* bk    = (const float*)d_in[4];
    const float* Wv    = (const float*)d_in[5];
    const float* bv    = (const float*)d_in[6];
    const float* gamma = (const float*)d_in[7];
    float* out = (float*)d_out;

    cudaFuncSetAttribute(proj_kernel,  cudaFuncAttributeMaxDynamicSharedMemorySize, PROJ_SMEM);
    cudaFuncSetAttribute(flash_kernel, cudaFuncAttributeMaxDynamicSharedMemorySize, FLASH_SMEM);

    prep_kernel<<<dim3(C_ / 32, N_ / 128, B_), 256>>>(x, Wq, bq, Wk, bk, Wv, bv);
    proj_kernel<<<dim3(4, (B_ * N_) / 128), 256, PROJ_SMEM>>>();
    flash_kernel<<<dim3(N_ / 64, B_), 256, FLASH_SMEM>>>(x, gamma, out);
}